// round 15
// baseline (speedup 1.0000x reference)
#include <cuda_runtime.h>

// Inputs (metadata order): z [8192*128] f32 (UNUSED), risk [B] f32, time [B] f32, event [B] i32.
// Output: single f32 scalar = mean hinge over pairs (time[i] < time[j] && event[i]==1).
//
// K1: simple per-thread atomic scatter into 32 time-buckets
//     (all rows -> g_J; event rows -> g_I with risk+1 prestored).
// K2: triangular grid over bucket pairs (bj >= bi), 528 blocks, TPB=256:
//     threads = 128 i-slots x 2 j-halves. bj > bi : FREE (3 ops/pair, closed-form
//     count). bj == bi : MIXED (exact strict per-pair compare). 4 accumulators
//     per thread break FADD chains. Last block finalizes and resets all state
//     (idempotent under CUDA-graph replay).

#define NB    32
#define CAP   8192
#define TPB   256
#define NTILE (NB * (NB + 1) / 2)     // 528

__device__ float2             g_J[NB * CAP];   // (risk, time) per time-bucket
__device__ float2             g_I[NB * CAP];   // (risk+1, time), event rows only
__device__ int                g_cJ[NB];        // bucket counts (zeroed at load / by finalize)
__device__ int                g_cI[NB];
__device__ double             g_total;
__device__ unsigned long long g_cnt;
__device__ unsigned int       g_done;

// ---------------- K1: bucket scatter (plain atomics) ----------------
__global__ void k_scatter(const float* __restrict__ risk,
                          const float* __restrict__ time_,
                          const int*   __restrict__ event,
                          int n) {
    int r = blockIdx.x * blockDim.x + threadIdx.x;
    if (r >= n) return;
    float t  = time_[r];
    float rk = risk[r];
    int b = (int)(t * (float)NB);
    b = b < 0 ? 0 : (b > NB - 1 ? NB - 1 : b);
    int d = atomicAdd(&g_cJ[b], 1);
    g_J[b * CAP + d] = make_float2(rk, t);
    if (event[r] == 1) {
        int di = atomicAdd(&g_cI[b], 1);
        g_I[b * CAP + di] = make_float2(rk + 1.0f, t);
    }
}

// ---------------- K2: triangular classified bucket-tile loop ----------------
__global__ __launch_bounds__(TPB) void k_tiles(float* __restrict__ out) {
    __shared__ float sjr[256];         // risk_j (pad 1e30 -> hinge 0)
    __shared__ int   sjt[256];         // time_j bits (pad -inf bits -> pred false)
    __shared__ float swsum[TPB / 32];
    __shared__ int   swcnt[TPB / 32];

    const int tid   = threadIdx.x;
    const int lane  = tid & 31;
    const int w     = tid >> 5;
    const int half  = tid >> 7;        // 0/1 : which 128-j half this thread sweeps
    const int islot = tid & 127;

    // triangular tile -> (bi, bj), bj >= bi   (uniform ~32-step scan)
    int bi = 0, rem = blockIdx.x;
    while (rem >= NB - bi) { rem -= NB - bi; bi++; }
    const int bj = bi + rem;

    float              s  = 0.0f;
    int                c  = 0;
    unsigned long long cf = 0ull;      // thread 0 only

    const int ni = g_cI[bi];
    const int nj = g_cJ[bj];

    if (ni > 0 && nj > 0) {
        const bool freeT = (bj > bi);
        if (freeT && tid == 0)
            cf = (unsigned long long)ni * (unsigned long long)nj;

        const float2* __restrict__ I = g_I + bi * CAP;
        const float2* __restrict__ J = g_J + bj * CAP;

        for (int j0 = 0; j0 < nj; j0 += 256) {       // block-uniform
            __syncthreads();                          // protect sj from prev phase
            {
                int jg = j0 + tid;
                float rj  = 1.0e30f;                  // pad: hinge contributes 0
                int   tjb = 0xff800000;               // pad: predicate never true
                if (jg < nj) { float2 v = J[jg]; rj = v.x; tjb = __float_as_int(v.y); }
                sjr[tid] = rj;
                sjt[tid] = tjb;
            }
            __syncthreads();

            const int kb = half * 128;

            for (int i0 = 0; i0 < ni; i0 += 128) {   // block-uniform
                int i = i0 + islot;
                if (i < ni) {
                    float2 u = I[i];
                    const float r0  = u.x;
                    const int   t0b = __float_as_int(u.y);

                    float a0 = 0.f, a1 = 0.f, a2 = 0.f, a3 = 0.f;
                    if (freeT) {
                        #pragma unroll 4
                        for (int k = 0; k < 128; k += 4) {
                            a0 += fmaxf(r0 - sjr[kb + k    ], 0.0f);
                            a1 += fmaxf(r0 - sjr[kb + k + 1], 0.0f);
                            a2 += fmaxf(r0 - sjr[kb + k + 2], 0.0f);
                            a3 += fmaxf(r0 - sjr[kb + k + 3], 0.0f);
                        }
                    } else {
                        int c0 = 0, c1 = 0, c2 = 0, c3 = 0;
                        #pragma unroll 4
                        for (int k = 0; k < 128; k += 4) {
                            bool p0 = sjt[kb + k    ] > t0b;
                            bool p1 = sjt[kb + k + 1] > t0b;
                            bool p2 = sjt[kb + k + 2] > t0b;
                            bool p3 = sjt[kb + k + 3] > t0b;
                            a0 += p0 ? fmaxf(r0 - sjr[kb + k    ], 0.0f) : 0.0f;
                            a1 += p1 ? fmaxf(r0 - sjr[kb + k + 1], 0.0f) : 0.0f;
                            a2 += p2 ? fmaxf(r0 - sjr[kb + k + 2], 0.0f) : 0.0f;
                            a3 += p3 ? fmaxf(r0 - sjr[kb + k + 3], 0.0f) : 0.0f;
                            c0 += (int)p0; c1 += (int)p1; c2 += (int)p2; c3 += (int)p3;
                        }
                        c += (c0 + c1) + (c2 + c3);
                    }
                    s += (a0 + a1) + (a2 + a3);
                }
            }
        }
    }

    // ---- reduce + global accumulate + finalize ----
    #pragma unroll
    for (int off = 16; off >= 1; off >>= 1) {
        s += __shfl_down_sync(0xffffffffu, s, off);
        c += __shfl_down_sync(0xffffffffu, c, off);
    }
    if (lane == 0) { swsum[w] = s; swcnt[w] = c; }
    __syncthreads();
    if (tid == 0) {
        float ss = 0.f; int cc = 0;
        #pragma unroll
        for (int q = 0; q < TPB / 32; q++) { ss += swsum[q]; cc += swcnt[q]; }
        unsigned long long ctot = (unsigned long long)cc + cf;
        if (ss != 0.0f)   atomicAdd(&g_total, (double)ss);
        if (ctot != 0ull) atomicAdd(&g_cnt, ctot);
        __threadfence();
        unsigned int prev = atomicAdd(&g_done, 1u);
        if (prev == (unsigned int)NTILE - 1u) {
            __threadfence();
            double tt = *(volatile double*)&g_total;
            unsigned long long cn = *(volatile unsigned long long*)&g_cnt;
            out[0] = (cn != 0ull) ? (float)(tt / (double)cn) : 0.0f;
            // reset all state: launch sequence idempotent for next graph replay
            #pragma unroll
            for (int b = 0; b < NB; b++) { g_cJ[b] = 0; g_cI[b] = 0; }
            g_total = 0.0;
            g_cnt   = 0ull;
            g_done  = 0u;
        }
    }
}

extern "C" void kernel_launch(void* const* d_in, const int* in_sizes, int n_in,
                              void* d_out, int out_size) {
    const float* risk  = (const float*)d_in[1];
    const float* time_ = (const float*)d_in[2];
    const int*   event = (const int*)d_in[3];
    const int n = in_sizes[1];

    k_scatter<<<(n + TPB - 1) / TPB, TPB>>>(risk, time_, event, n);
    k_tiles<<<NTILE, TPB>>>((float*)d_out);
}